// round 4
// baseline (speedup 1.0000x reference)
#include <cuda_runtime.h>
#include <mma.h>
#include <cstdint>
#include <cstddef>

using namespace nvcuda;

// ============================================================================
// Problem constants
// ============================================================================
static constexpr int BATCH  = 16384;
static constexpr int IN_DIM = 512;
static constexpr int UNITS  = 256;
static constexpr int NEXP   = 8;
static constexpr int NTASK  = 4;
static constexpr int NCOL   = UNITS * NEXP;   // 2048, n = u*8+e
static constexpr int GCOL   = NEXP * NTASK;   // 32,   g = e*4+t

// Tiling
static constexpr int BM     = 128;
static constexpr int BN     = 128;            // 16 units x 8 experts per tile
static constexpr int KC     = 32;
static constexpr int KSTEPS = IN_DIM / KC;    // 16
static constexpr int STAGES = 3;

// Shared memory layout (floats)
static constexpr int A_LD          = KC + 4;           // 36
static constexpr int B_LD          = BN + 4;           // 132
static constexpr int A_TILE_FLOATS = BM * A_LD;        // 4608
static constexpr int B_TILE_FLOATS = KC * B_LD;        // 4224
static constexpr int STAGE_FLOATS  = A_TILE_FLOATS + B_TILE_FLOATS;  // 8832
static constexpr int HDR_FLOATS    = 128;              // be slice
static constexpr int SMEM_FLOATS   = HDR_FLOATS + STAGES * STAGE_FLOATS;
static constexpr int SMEM_BYTES    = SMEM_FLOATS * 4;  // 106496
static constexpr int C_LD          = BN + 4;           // 132 (epilogue staging)

// ============================================================================
// Device scratch (no allocations allowed): softmaxed gates [b][e*4+t]
// ============================================================================
__device__ float g_gates[BATCH * GCOL];

// ============================================================================
// Helpers
// ============================================================================
__device__ __forceinline__ uint32_t smem_u32(const void* p) {
    uint32_t a;
    asm("{ .reg .u64 t; cvta.to.shared.u64 t, %1; cvt.u32.u64 %0, t; }" : "=r"(a) : "l"(p));
    return a;
}
__device__ __forceinline__ void cp_async16(uint32_t dst, const void* src) {
    asm volatile("cp.async.cg.shared.global [%0], [%1], 16;\n" :: "r"(dst), "l"(src));
}
#define CP_COMMIT()       asm volatile("cp.async.commit_group;\n" ::: "memory")
#define CP_WAIT_GROUP_1() asm volatile("cp.async.wait_group 1;\n" ::: "memory")

// ============================================================================
// Gating kernel: gate[b][e*4+t] = softmax_e(x[b] @ Wg[:, e, t] + bg[e,t])
// 4 rows per 128-thread block.
// ============================================================================
__global__ void __launch_bounds__(128)
gate_kernel(const float* __restrict__ x, const float* __restrict__ Wg,
            const float* __restrict__ bg) {
    __shared__ float xs[4][IN_DIM];
    __shared__ float ls[4][GCOL];
    const int tid = threadIdx.x;
    const int b0  = blockIdx.x * 4;

    for (int idx = tid; idx < 4 * IN_DIM; idx += 128)
        xs[idx >> 9][idx & 511] = x[(size_t)(b0 + (idx >> 9)) * IN_DIM + (idx & 511)];
    __syncthreads();

    const int r = tid >> 5, g = tid & 31;
    float acc = 0.f;
    #pragma unroll 8
    for (int k = 0; k < IN_DIM; k++)
        acc += xs[r][k] * Wg[(size_t)k * GCOL + g];
    ls[r][g] = acc + bg[g];
    __syncthreads();

    if (tid < 16) {
        const int rr = tid >> 2, t = tid & 3;
        float v[NEXP], m = -3.4e38f;
        #pragma unroll
        for (int e = 0; e < NEXP; e++) { v[e] = ls[rr][e * 4 + t]; m = fmaxf(m, v[e]); }
        float den = 0.f;
        #pragma unroll
        for (int e = 0; e < NEXP; e++) { v[e] = expf(v[e] - m); den += v[e]; }
        const float inv = 1.f / den;
        #pragma unroll
        for (int e = 0; e < NEXP; e++)
            g_gates[(size_t)(b0 + rr) * GCOL + e * 4 + t] = v[e] * inv;
    }
}

// ============================================================================
// Main kernel: expert GEMM (wmma tf32) + fused bias/ReLU/combine epilogue
// ============================================================================
__global__ void __launch_bounds__(256)
moe_wmma_kernel(const float* __restrict__ x, const float* __restrict__ We,
                const float* __restrict__ be, float* __restrict__ out) {
    extern __shared__ float smem[];
    float* sbe    = smem;
    float* stage0 = smem + HDR_FLOATS;

    const int tid = threadIdx.x;
    const int wid = tid >> 5;
    const int warp_m = wid >> 1;        // 0..3 -> rows warp_m*32
    const int warp_n = wid & 1;         // 0..1 -> cols warp_n*64

    const int n_tile = blockIdx.x & 15;
    const int b_tile = blockIdx.x >> 4;
    const int b0 = b_tile * BM;
    const int n0 = n_tile * BN;

    if (tid < BN) sbe[tid] = be[n0 + tid];

    wmma::fragment<wmma::accumulator, 16, 16, 8, float> acc[2][4];
    #pragma unroll
    for (int i = 0; i < 2; i++)
        #pragma unroll
        for (int j = 0; j < 4; j++)
            wmma::fill_fragment(acc[i][j], 0.f);

    auto load_stage = [&](int slot, int chunk) {
        float* As = stage0 + slot * STAGE_FLOATS;
        float* Bs = As + A_TILE_FLOATS;
        const uint32_t aB = smem_u32(As);
        const uint32_t bB = smem_u32(Bs);
        const int k0 = chunk * KC;
        // A: 128 rows x 32 floats = 1024 x 16B chunks
        #pragma unroll
        for (int i = 0; i < 4; i++) {
            int idx = tid + i * 256;
            int row = idx >> 3, c16 = idx & 7;
            cp_async16(aB + (uint32_t)(row * A_LD * 4 + c16 * 16),
                       x + (size_t)(b0 + row) * IN_DIM + k0 + c16 * 4);
        }
        // B: 32 rows x 128 floats = 1024 x 16B chunks (We is [k][n] row-major)
        #pragma unroll
        for (int i = 0; i < 4; i++) {
            int idx = tid + i * 256;
            int row = idx >> 5, c16 = idx & 31;
            cp_async16(bB + (uint32_t)(row * B_LD * 4 + c16 * 16),
                       We + (size_t)(k0 + row) * NCOL + n0 + c16 * 4);
        }
    };

    auto compute_stage = [&](int slot) {
        float* As = stage0 + slot * STAGE_FLOATS;
        float* Bs = As + A_TILE_FLOATS;
        #pragma unroll
        for (int ks = 0; ks < KC / 8; ks++) {
            wmma::fragment<wmma::matrix_a, 16, 16, 8, wmma::precision::tf32, wmma::row_major> af[2];
            wmma::fragment<wmma::matrix_b, 16, 16, 8, wmma::precision::tf32, wmma::row_major> bf[4];
            #pragma unroll
            for (int i = 0; i < 2; i++) {
                wmma::load_matrix_sync(af[i], As + (warp_m * 32 + i * 16) * A_LD + ks * 8, A_LD);
                #pragma unroll
                for (int e = 0; e < af[i].num_elements; e++)
                    af[i].x[e] = wmma::__float_to_tf32(af[i].x[e]);
            }
            #pragma unroll
            for (int j = 0; j < 4; j++) {
                wmma::load_matrix_sync(bf[j], Bs + (ks * 8) * B_LD + warp_n * 64 + j * 16, B_LD);
                #pragma unroll
                for (int e = 0; e < bf[j].num_elements; e++)
                    bf[j].x[e] = wmma::__float_to_tf32(bf[j].x[e]);
            }
            #pragma unroll
            for (int i = 0; i < 2; i++)
                #pragma unroll
                for (int j = 0; j < 4; j++)
                    wmma::mma_sync(acc[i][j], af[i], bf[j], acc[i][j]);
        }
    };

    // Prologue
    load_stage(0, 0); CP_COMMIT();
    load_stage(1, 1); CP_COMMIT();

    // Main loop
    for (int kt = 0; kt < KSTEPS; kt++) {
        CP_WAIT_GROUP_1();
        __syncthreads();
        const int next = kt + 2;
        if (next < KSTEPS) load_stage(next % STAGES, next);
        CP_COMMIT();
        compute_stage(kt % STAGES);
    }

    // ------------------------------------------------------------------
    // Epilogue: stage C through smem, then bias+ReLU+gate combine
    // ------------------------------------------------------------------
    __syncthreads();
    float* Cs = stage0;   // 128 x C_LD floats = 67.6 KB, fits in stage region
    #pragma unroll
    for (int i = 0; i < 2; i++)
        #pragma unroll
        for (int j = 0; j < 4; j++)
            wmma::store_matrix_sync(Cs + (warp_m * 32 + i * 16) * C_LD + warp_n * 64 + j * 16,
                                    acc[i][j], C_LD, wmma::mem_row_major);
    __syncthreads();

    const int r = tid >> 1;       // row in tile
    const int h = tid & 1;        // column half (8 units each)
    const int b = b0 + r;

    float gate[GCOL];
    {
        const float4* gp = (const float4*)(g_gates + (size_t)b * GCOL);
        #pragma unroll
        for (int q = 0; q < 8; q++) ((float4*)gate)[q] = gp[q];
    }

    float accu[8][NTASK];
    #pragma unroll
    for (int u = 0; u < 8; u++)
        #pragma unroll
        for (int t = 0; t < NTASK; t++) accu[u][t] = 0.f;

    #pragma unroll
    for (int u = 0; u < 8; u++) {
        const int nl = (h * 8 + u) * 8;
        #pragma unroll
        for (int e = 0; e < NEXP; e++) {
            float v = Cs[r * C_LD + nl + e] + sbe[nl + e];
            v = fmaxf(v, 0.f);
            #pragma unroll
            for (int t = 0; t < NTASK; t++) accu[u][t] += v * gate[e * 4 + t];
        }
    }

    float* ob = out + (size_t)b * UNITS + n_tile * 16 + h * 8;
    #pragma unroll
    for (int t = 0; t < NTASK; t++) {
        float4 o0 = make_float4(accu[0][t], accu[1][t], accu[2][t], accu[3][t]);
        float4 o1 = make_float4(accu[4][t], accu[5][t], accu[6][t], accu[7][t]);
        *(float4*)(ob + (size_t)t * BATCH * UNITS)     = o0;
        *(float4*)(ob + (size_t)t * BATCH * UNITS + 4) = o1;
    }
}

// ============================================================================
// Launch
// ============================================================================
extern "C" void kernel_launch(void* const* d_in, const int* in_sizes, int n_in,
                              void* d_out, int out_size) {
    const float* x  = (const float*)d_in[0];
    const float* We = (const float*)d_in[1];
    const float* be = (const float*)d_in[2];
    const float* Wg = (const float*)d_in[3];
    const float* bg = (const float*)d_in[4];
    float* out = (float*)d_out;

    cudaFuncSetAttribute(moe_wmma_kernel, cudaFuncAttributeMaxDynamicSharedMemorySize, SMEM_BYTES);

    gate_kernel<<<BATCH / 4, 128>>>(x, Wg, bg);
    moe_wmma_kernel<<<(BATCH / BM) * (NCOL / BN), 256, SMEM_BYTES>>>(x, We, be, out);
}

// round 5
// speedup vs baseline: 1.1127x; 1.1127x over previous
#include <cuda_runtime.h>
#include <mma.h>
#include <cstdint>
#include <cstddef>

using namespace nvcuda;

// ============================================================================
// Problem constants
// ============================================================================
static constexpr int BATCH  = 16384;
static constexpr int IN_DIM = 512;
static constexpr int UNITS  = 256;
static constexpr int NEXP   = 8;
static constexpr int NTASK  = 4;
static constexpr int NCOL   = UNITS * NEXP;   // 2048, n = u*8+e
static constexpr int GCOL   = NEXP * NTASK;   // 32,   g = e*4+t

// Tiling
static constexpr int BM     = 256;
static constexpr int BN     = 128;            // 16 units x 8 experts per tile
static constexpr int KC     = 32;
static constexpr int KSTEPS = IN_DIM / KC;    // 16
static constexpr int STAGES = 3;
static constexpr int NTHREADS = 512;          // 16 warps, 4x4 warp grid

// Shared memory layout (floats)
static constexpr int A_LD          = KC + 4;           // 36
static constexpr int B_LD          = BN + 4;           // 132
static constexpr int A_TILE_FLOATS = BM * A_LD;        // 9216
static constexpr int B_TILE_FLOATS = KC * B_LD;        // 4224
static constexpr int STAGE_FLOATS  = A_TILE_FLOATS + B_TILE_FLOATS;  // 13440
static constexpr int HDR_FLOATS    = 128;              // be slice
static constexpr int SMEM_FLOATS   = HDR_FLOATS + STAGES * STAGE_FLOATS;
static constexpr int SMEM_BYTES    = SMEM_FLOATS * 4;  // 161792
static constexpr int C_LD          = BN + 4;           // 132 (epilogue staging, 256*132*4=135KB)

// ============================================================================
// Device scratch (no allocations allowed)
// ============================================================================
__device__ float  g_gates[BATCH * GCOL];        // softmaxed gates [b][e*4+t]
__device__ float4 g_xr4 [BATCH * IN_DIM / 4];   // tf32-rounded x   (32 MB)
__device__ float4 g_Wer4[IN_DIM * NCOL / 4];    // tf32-rounded We  ( 4 MB), [k][n]

// ============================================================================
// Helpers
// ============================================================================
__device__ __forceinline__ uint32_t smem_u32(const void* p) {
    uint32_t a;
    asm("{ .reg .u64 t; cvta.to.shared.u64 t, %1; cvt.u32.u64 %0, t; }" : "=r"(a) : "l"(p));
    return a;
}
__device__ __forceinline__ float tf32_rn(float f) {
    uint32_t o; asm("cvt.rn.tf32.f32 %0, %1;" : "=r"(o) : "f"(f));
    return __uint_as_float(o);
}
__device__ __forceinline__ void cp_async16(uint32_t dst, const void* src) {
    asm volatile("cp.async.cg.shared.global [%0], [%1], 16;\n" :: "r"(dst), "l"(src));
}
#define CP_COMMIT()       asm volatile("cp.async.commit_group;\n" ::: "memory")
#define CP_WAIT_GROUP_1() asm volatile("cp.async.wait_group 1;\n" ::: "memory")

// ============================================================================
// Prep kernels: RN-round inputs to tf32 once (removes all in-loop cvts)
// ============================================================================
__global__ void __launch_bounds__(256)
prep_x_kernel(const float4* __restrict__ x4) {
    size_t i = (size_t)blockIdx.x * blockDim.x + threadIdx.x;
    float4 v = x4[i];
    v.x = tf32_rn(v.x); v.y = tf32_rn(v.y); v.z = tf32_rn(v.z); v.w = tf32_rn(v.w);
    g_xr4[i] = v;
}
__global__ void __launch_bounds__(256)
prep_We_kernel(const float4* __restrict__ We4) {
    size_t i = (size_t)blockIdx.x * blockDim.x + threadIdx.x;
    float4 v = We4[i];
    v.x = tf32_rn(v.x); v.y = tf32_rn(v.y); v.z = tf32_rn(v.z); v.w = tf32_rn(v.w);
    g_Wer4[i] = v;
}

// ============================================================================
// Gating kernel: gate[b][e*4+t] = softmax_e(x[b] @ Wg[:, e, t] + bg[e,t])
// 16 rows per 512-thread block; 4 independent FFMA chains per thread.
// ============================================================================
__global__ void __launch_bounds__(512)
gate_kernel(const float* __restrict__ x, const float* __restrict__ Wg,
            const float* __restrict__ bg) {
    __shared__ float xs[16][IN_DIM];
    __shared__ float ls[16][GCOL];
    const int tid = threadIdx.x;
    const int b0  = blockIdx.x * 16;

    for (int idx = tid; idx < 16 * IN_DIM; idx += 512)
        xs[idx >> 9][idx & 511] = x[(size_t)(b0 + (idx >> 9)) * IN_DIM + (idx & 511)];
    __syncthreads();

    const int r = tid >> 5, g = tid & 31;
    float a0 = 0.f, a1 = 0.f, a2 = 0.f, a3 = 0.f;
    #pragma unroll 4
    for (int k = 0; k < IN_DIM; k += 4) {
        a0 += xs[r][k]     * Wg[(size_t)(k)     * GCOL + g];
        a1 += xs[r][k + 1] * Wg[(size_t)(k + 1) * GCOL + g];
        a2 += xs[r][k + 2] * Wg[(size_t)(k + 2) * GCOL + g];
        a3 += xs[r][k + 3] * Wg[(size_t)(k + 3) * GCOL + g];
    }
    ls[r][g] = (a0 + a1) + (a2 + a3) + bg[g];
    __syncthreads();

    if (tid < 64) {
        const int rr = tid >> 2, t = tid & 3;
        float v[NEXP], m = -3.4e38f;
        #pragma unroll
        for (int e = 0; e < NEXP; e++) { v[e] = ls[rr][e * 4 + t]; m = fmaxf(m, v[e]); }
        float den = 0.f;
        #pragma unroll
        for (int e = 0; e < NEXP; e++) { v[e] = expf(v[e] - m); den += v[e]; }
        const float inv = 1.f / den;
        #pragma unroll
        for (int e = 0; e < NEXP; e++)
            g_gates[(size_t)(b0 + rr) * GCOL + e * 4 + t] = v[e] * inv;
    }
}

// ============================================================================
// Main kernel: expert GEMM (wmma tf32, pre-rounded) + fused epilogue
// ============================================================================
__global__ void __launch_bounds__(512, 1)
moe_wmma_kernel(const float* __restrict__ be, float* __restrict__ out) {
    extern __shared__ float smem[];
    float* sbe    = smem;
    float* stage0 = smem + HDR_FLOATS;

    const float* x  = (const float*)g_xr4;
    const float* We = (const float*)g_Wer4;

    const int tid = threadIdx.x;
    const int wid = tid >> 5;
    const int warp_m = wid >> 2;        // 0..3 -> rows warp_m*64
    const int warp_n = wid & 3;         // 0..3 -> cols warp_n*32

    const int n_tile = blockIdx.x & 15;
    const int b_tile = blockIdx.x >> 4;
    const int b0 = b_tile * BM;
    const int n0 = n_tile * BN;

    if (tid < BN) sbe[tid] = be[n0 + tid];

    wmma::fragment<wmma::accumulator, 16, 16, 8, float> acc[4][2];
    #pragma unroll
    for (int i = 0; i < 4; i++)
        #pragma unroll
        for (int j = 0; j < 2; j++)
            wmma::fill_fragment(acc[i][j], 0.f);

    auto load_stage = [&](int slot, int chunk) {
        float* As = stage0 + slot * STAGE_FLOATS;
        float* Bs = As + A_TILE_FLOATS;
        const uint32_t aB = smem_u32(As);
        const uint32_t bB = smem_u32(Bs);
        const int k0 = chunk * KC;
        // A: 256 rows x 32 floats = 2048 x 16B chunks -> 4 per thread
        #pragma unroll
        for (int i = 0; i < 4; i++) {
            int idx = tid + i * 512;
            int row = idx >> 3, c16 = idx & 7;
            cp_async16(aB + (uint32_t)(row * A_LD * 4 + c16 * 16),
                       x + (size_t)(b0 + row) * IN_DIM + k0 + c16 * 4);
        }
        // B: 32 rows x 128 floats = 1024 x 16B chunks -> 2 per thread
        #pragma unroll
        for (int i = 0; i < 2; i++) {
            int idx = tid + i * 512;
            int row = idx >> 5, c16 = idx & 31;
            cp_async16(bB + (uint32_t)(row * B_LD * 4 + c16 * 16),
                       We + (size_t)(k0 + row) * NCOL + n0 + c16 * 4);
        }
    };

    auto compute_stage = [&](int slot) {
        float* As = stage0 + slot * STAGE_FLOATS;
        float* Bs = As + A_TILE_FLOATS;
        #pragma unroll
        for (int ks = 0; ks < KC / 8; ks++) {
            wmma::fragment<wmma::matrix_a, 16, 16, 8, wmma::precision::tf32, wmma::row_major> af[4];
            wmma::fragment<wmma::matrix_b, 16, 16, 8, wmma::precision::tf32, wmma::row_major> bf[2];
            #pragma unroll
            for (int i = 0; i < 4; i++)
                wmma::load_matrix_sync(af[i], As + (warp_m * 64 + i * 16) * A_LD + ks * 8, A_LD);
            #pragma unroll
            for (int j = 0; j < 2; j++)
                wmma::load_matrix_sync(bf[j], Bs + (ks * 8) * B_LD + warp_n * 32 + j * 16, B_LD);
            #pragma unroll
            for (int i = 0; i < 4; i++)
                #pragma unroll
                for (int j = 0; j < 2; j++)
                    wmma::mma_sync(acc[i][j], af[i], bf[j], acc[i][j]);
        }
    };

    // Prologue
    load_stage(0, 0); CP_COMMIT();
    load_stage(1, 1); CP_COMMIT();

    // Main loop
    for (int kt = 0; kt < KSTEPS; kt++) {
        CP_WAIT_GROUP_1();
        __syncthreads();
        const int next = kt + 2;
        if (next < KSTEPS) load_stage(next % STAGES, next);
        CP_COMMIT();
        compute_stage(kt % STAGES);
    }

    // ------------------------------------------------------------------
    // Epilogue: stage C through smem, then bias+ReLU+gate combine
    // ------------------------------------------------------------------
    __syncthreads();
    float* Cs = stage0;   // 256 x 132 floats = 135 KB, fits in 158 KB stage region
    #pragma unroll
    for (int i = 0; i < 4; i++)
        #pragma unroll
        for (int j = 0; j < 2; j++)
            wmma::store_matrix_sync(Cs + (warp_m * 64 + i * 16) * C_LD + warp_n * 32 + j * 16,
                                    acc[i][j], C_LD, wmma::mem_row_major);
    __syncthreads();

    const int r = tid >> 1;       // row in tile (0..255)
    const int h = tid & 1;        // column half (8 units each)
    const int b = b0 + r;

    float gate[GCOL];
    {
        const float4* gp = (const float4*)(g_gates + (size_t)b * GCOL);
        #pragma unroll
        for (int q = 0; q < 8; q++) ((float4*)gate)[q] = gp[q];
    }

    float accu[8][NTASK];
    #pragma unroll
    for (int u = 0; u < 8; u++)
        #pragma unroll
        for (int t = 0; t < NTASK; t++) accu[u][t] = 0.f;

    #pragma unroll
    for (int u = 0; u < 8; u++) {
        const int nl = (h * 8 + u) * 8;
        #pragma unroll
        for (int e = 0; e < NEXP; e++) {
            float v = Cs[r * C_LD + nl + e] + sbe[nl + e];
            v = fmaxf(v, 0.f);
            #pragma unroll
            for (int t = 0; t < NTASK; t++) accu[u][t] += v * gate[e * 4 + t];
        }
    }

    float* ob = out + (size_t)b * UNITS + n_tile * 16 + h * 8;
    #pragma unroll
    for (int t = 0; t < NTASK; t++) {
        float4 o0 = make_float4(accu[0][t], accu[1][t], accu[2][t], accu[3][t]);
        float4 o1 = make_float4(accu[4][t], accu[5][t], accu[6][t], accu[7][t]);
        *(float4*)(ob + (size_t)t * BATCH * UNITS)     = o0;
        *(float4*)(ob + (size_t)t * BATCH * UNITS + 4) = o1;
    }
}

// ============================================================================
// Launch
// ============================================================================
extern "C" void kernel_launch(void* const* d_in, const int* in_sizes, int n_in,
                              void* d_out, int out_size) {
    const float* x  = (const float*)d_in[0];
    const float* We = (const float*)d_in[1];
    const float* be = (const float*)d_in[2];
    const float* Wg = (const float*)d_in[3];
    const float* bg = (const float*)d_in[4];
    float* out = (float*)d_out;

    cudaFuncSetAttribute(moe_wmma_kernel, cudaFuncAttributeMaxDynamicSharedMemorySize, SMEM_BYTES);

    prep_x_kernel <<<BATCH * IN_DIM / 4 / 256, 256>>>((const float4*)x);
    prep_We_kernel<<<IN_DIM * NCOL / 4 / 256, 256>>>((const float4*)We);
    gate_kernel<<<BATCH / 16, 512>>>(x, Wg, bg);
    moe_wmma_kernel<<<(BATCH / BM) * (NCOL / BN), 512, SMEM_BYTES>>>(be, out);
}

// round 6
// speedup vs baseline: 1.1941x; 1.0732x over previous
#include <cuda_runtime.h>
#include <mma.h>
#include <cstdint>
#include <cstddef>

using namespace nvcuda;

// ============================================================================
// Problem constants
// ============================================================================
static constexpr int BATCH  = 16384;
static constexpr int IN_DIM = 512;
static constexpr int UNITS  = 256;
static constexpr int NEXP   = 8;
static constexpr int NTASK  = 4;
static constexpr int NCOL   = UNITS * NEXP;   // 2048, n = u*8+e
static constexpr int GCOL   = NEXP * NTASK;   // 32,   g = e*4+t

// Tiling
static constexpr int BM     = 128;
static constexpr int BN     = 128;            // 16 units x 8 experts per tile
static constexpr int KC     = 32;
static constexpr int KSTEPS = IN_DIM / KC;    // 16
static constexpr int STAGES = 3;
static constexpr int NTHREADS = 256;          // 8 warps, 2x4 warp grid

// Shared memory layout (floats)
static constexpr int A_LD          = KC + 4;           // 36
static constexpr int B_LD          = BN + 4;           // 132
static constexpr int A_TILE_FLOATS = BM * A_LD;        // 4608
static constexpr int B_TILE_FLOATS = KC * B_LD;        // 4224
static constexpr int STAGE_FLOATS  = A_TILE_FLOATS + B_TILE_FLOATS;  // 8832
static constexpr int HDR_FLOATS    = 128;              // be slice
static constexpr int SMEM_FLOATS   = HDR_FLOATS + STAGES * STAGE_FLOATS;
static constexpr int SMEM_BYTES    = SMEM_FLOATS * 4;  // 106496 (x2 CTA = 208 KB <= 227 KB)
static constexpr int C_LD          = BN + 4;           // 132 (staging: 128*132*4 = 67.6 KB)

// ============================================================================
// Device scratch (no allocations allowed)
// ============================================================================
__device__ float  g_gates[BATCH * GCOL];        // softmaxed gates [b][e*4+t]
__device__ float4 g_xr4 [BATCH * IN_DIM / 4];   // tf32-rounded x   (32 MB)
__device__ float4 g_Wer4[IN_DIM * NCOL / 4];    // tf32-rounded We  ( 4 MB), [k][n]

// ============================================================================
// Helpers
// ============================================================================
__device__ __forceinline__ uint32_t smem_u32(const void* p) {
    uint32_t a;
    asm("{ .reg .u64 t; cvta.to.shared.u64 t, %1; cvt.u32.u64 %0, t; }" : "=r"(a) : "l"(p));
    return a;
}
__device__ __forceinline__ float tf32_rn(float f) {
    uint32_t o; asm("cvt.rn.tf32.f32 %0, %1;" : "=r"(o) : "f"(f));
    return __uint_as_float(o);
}
__device__ __forceinline__ void cp_async16(uint32_t dst, const void* src) {
    asm volatile("cp.async.cg.shared.global [%0], [%1], 16;\n" :: "r"(dst), "l"(src));
}
#define CP_COMMIT()       asm volatile("cp.async.commit_group;\n" ::: "memory")
#define CP_WAIT_GROUP_1() asm volatile("cp.async.wait_group 1;\n" ::: "memory")

// ============================================================================
// prep We: RN-round to tf32 once
// ============================================================================
__global__ void __launch_bounds__(256)
prep_We_kernel(const float4* __restrict__ We4) {
    size_t i = (size_t)blockIdx.x * blockDim.x + threadIdx.x;
    float4 v = We4[i];
    v.x = tf32_rn(v.x); v.y = tf32_rn(v.y); v.z = tf32_rn(v.z); v.w = tf32_rn(v.w);
    g_Wer4[i] = v;
}

// ============================================================================
// Gating kernel (also writes tf32-rounded x — fuses prep_x):
//   g_xr4 = rn(x); gate[b][e*4+t] = softmax_e(x[b] @ Wg[:, e, t] + bg[e,t])
// 16 rows per 512-thread block.
// ============================================================================
__global__ void __launch_bounds__(512)
gate_kernel(const float4* __restrict__ x4, const float* __restrict__ Wg,
            const float* __restrict__ bg) {
    __shared__ float xs[16][IN_DIM];
    __shared__ float ls[16][GCOL];
    const int tid = threadIdx.x;
    const int b0  = blockIdx.x * 16;

    // load + round + stash to smem AND to g_xr4 (16*128 float4s, 4 per thread)
    #pragma unroll
    for (int i = 0; i < 4; i++) {
        int idx = tid + i * 512;          // float4 index within tile
        int rr = idx >> 7, c = idx & 127;
        size_t gi = (size_t)(b0 + rr) * (IN_DIM / 4) + c;
        float4 v = x4[gi];
        v.x = tf32_rn(v.x); v.y = tf32_rn(v.y); v.z = tf32_rn(v.z); v.w = tf32_rn(v.w);
        *(float4*)&xs[rr][c * 4] = v;
        g_xr4[gi] = v;
    }
    __syncthreads();

    const int r = tid >> 5, g = tid & 31;
    float a0 = 0.f, a1 = 0.f, a2 = 0.f, a3 = 0.f;
    #pragma unroll 4
    for (int k = 0; k < IN_DIM; k += 4) {
        a0 += xs[r][k]     * Wg[(size_t)(k)     * GCOL + g];
        a1 += xs[r][k + 1] * Wg[(size_t)(k + 1) * GCOL + g];
        a2 += xs[r][k + 2] * Wg[(size_t)(k + 2) * GCOL + g];
        a3 += xs[r][k + 3] * Wg[(size_t)(k + 3) * GCOL + g];
    }
    ls[r][g] = (a0 + a1) + (a2 + a3) + bg[g];
    __syncthreads();

    if (tid < 64) {
        const int rr = tid >> 2, t = tid & 3;
        float v[NEXP], m = -3.4e38f;
        #pragma unroll
        for (int e = 0; e < NEXP; e++) { v[e] = ls[rr][e * 4 + t]; m = fmaxf(m, v[e]); }
        float den = 0.f;
        #pragma unroll
        for (int e = 0; e < NEXP; e++) { v[e] = expf(v[e] - m); den += v[e]; }
        const float inv = 1.f / den;
        #pragma unroll
        for (int e = 0; e < NEXP; e++)
            g_gates[(size_t)(b0 + rr) * GCOL + e * 4 + t] = v[e] * inv;
    }
}

// ============================================================================
// Main kernel: expert GEMM (wmma tf32, pre-rounded) + fused epilogue
// 256 threads, 2 CTAs/SM (reg-capped at 128 by launch bounds).
// ============================================================================
__global__ void __launch_bounds__(NTHREADS, 2)
moe_wmma_kernel(const float* __restrict__ be, float* __restrict__ out) {
    extern __shared__ float smem[];
    float* sbe    = smem;
    float* stage0 = smem + HDR_FLOATS;

    const float* x  = (const float*)g_xr4;
    const float* We = (const float*)g_Wer4;

    const int tid = threadIdx.x;
    const int wid = tid >> 5;
    const int warp_m = wid >> 2;        // 0..1 -> rows warp_m*64
    const int warp_n = wid & 3;         // 0..3 -> cols warp_n*32

    const int n_tile = blockIdx.x & 15;
    const int b_tile = blockIdx.x >> 4;
    const int b0 = b_tile * BM;
    const int n0 = n_tile * BN;

    if (tid < BN) sbe[tid] = be[n0 + tid];

    wmma::fragment<wmma::accumulator, 16, 16, 8, float> acc[4][2];
    #pragma unroll
    for (int i = 0; i < 4; i++)
        #pragma unroll
        for (int j = 0; j < 2; j++)
            wmma::fill_fragment(acc[i][j], 0.f);

    auto load_stage = [&](int slot, int chunk) {
        float* As = stage0 + slot * STAGE_FLOATS;
        float* Bs = As + A_TILE_FLOATS;
        const uint32_t aB = smem_u32(As);
        const uint32_t bB = smem_u32(Bs);
        const int k0 = chunk * KC;
        // A: 128 rows x 32 floats = 1024 x 16B chunks -> 4 per thread
        #pragma unroll
        for (int i = 0; i < 4; i++) {
            int idx = tid + i * 256;
            int row = idx >> 3, c16 = idx & 7;
            cp_async16(aB + (uint32_t)(row * A_LD * 4 + c16 * 16),
                       x + (size_t)(b0 + row) * IN_DIM + k0 + c16 * 4);
        }
        // B: 32 rows x 128 floats = 1024 x 16B chunks -> 4 per thread
        #pragma unroll
        for (int i = 0; i < 4; i++) {
            int idx = tid + i * 256;
            int row = idx >> 5, c16 = idx & 31;
            cp_async16(bB + (uint32_t)(row * B_LD * 4 + c16 * 16),
                       We + (size_t)(k0 + row) * NCOL + n0 + c16 * 4);
        }
    };

    auto compute_stage = [&](int slot) {
        float* As = stage0 + slot * STAGE_FLOATS;
        float* Bs = As + A_TILE_FLOATS;
        #pragma unroll
        for (int ks = 0; ks < KC / 8; ks++) {
            wmma::fragment<wmma::matrix_a, 16, 16, 8, wmma::precision::tf32, wmma::row_major> af[4];
            wmma::fragment<wmma::matrix_b, 16, 16, 8, wmma::precision::tf32, wmma::row_major> bf[2];
            #pragma unroll
            for (int i = 0; i < 4; i++)
                wmma::load_matrix_sync(af[i], As + (warp_m * 64 + i * 16) * A_LD + ks * 8, A_LD);
            #pragma unroll
            for (int j = 0; j < 2; j++)
                wmma::load_matrix_sync(bf[j], Bs + (ks * 8) * B_LD + warp_n * 32 + j * 16, B_LD);
            #pragma unroll
            for (int i = 0; i < 4; i++)
                #pragma unroll
                for (int j = 0; j < 2; j++)
                    wmma::mma_sync(acc[i][j], af[i], bf[j], acc[i][j]);
        }
    };

    // Prologue
    load_stage(0, 0); CP_COMMIT();
    load_stage(1, 1); CP_COMMIT();

    // Main loop
    for (int kt = 0; kt < KSTEPS; kt++) {
        CP_WAIT_GROUP_1();
        __syncthreads();
        const int next = kt + 2;
        if (next < KSTEPS) load_stage(next % STAGES, next);
        CP_COMMIT();
        compute_stage(kt % STAGES);
    }

    // ------------------------------------------------------------------
    // Epilogue: stage C through smem, then bias+ReLU+gate combine
    // ------------------------------------------------------------------
    __syncthreads();
    float* Cs = stage0;   // 128 x 132 floats = 67.6 KB, fits in stage region
    #pragma unroll
    for (int i = 0; i < 4; i++)
        #pragma unroll
        for (int j = 0; j < 2; j++)
            wmma::store_matrix_sync(Cs + (warp_m * 64 + i * 16) * C_LD + warp_n * 32 + j * 16,
                                    acc[i][j], C_LD, wmma::mem_row_major);
    __syncthreads();

    const int r = tid >> 1;       // row in tile (0..127)
    const int h = tid & 1;        // column half (8 units each)
    const int b = b0 + r;

    float gate[GCOL];
    {
        const float4* gp = (const float4*)(g_gates + (size_t)b * GCOL);
        #pragma unroll
        for (int q = 0; q < 8; q++) ((float4*)gate)[q] = gp[q];
    }

    float accu[8][NTASK];
    #pragma unroll
    for (int u = 0; u < 8; u++)
        #pragma unroll
        for (int t = 0; t < NTASK; t++) accu[u][t] = 0.f;

    #pragma unroll
    for (int u = 0; u < 8; u++) {
        const int nl = (h * 8 + u) * 8;
        #pragma unroll
        for (int e = 0; e < NEXP; e++) {
            float v = Cs[r * C_LD + nl + e] + sbe[nl + e];
            v = fmaxf(v, 0.f);
            #pragma unroll
            for (int t = 0; t < NTASK; t++) accu[u][t] += v * gate[e * 4 + t];
        }
    }

    float* ob = out + (size_t)b * UNITS + n_tile * 16 + h * 8;
    #pragma unroll
    for (int t = 0; t < NTASK; t++) {
        float4 o0 = make_float4(accu[0][t], accu[1][t], accu[2][t], accu[3][t]);
        float4 o1 = make_float4(accu[4][t], accu[5][t], accu[6][t], accu[7][t]);
        *(float4*)(ob + (size_t)t * BATCH * UNITS)     = o0;
        *(float4*)(ob + (size_t)t * BATCH * UNITS + 4) = o1;
    }
}

// ============================================================================
// Launch
// ============================================================================
extern "C" void kernel_launch(void* const* d_in, const int* in_sizes, int n_in,
                              void* d_out, int out_size) {
    const float* x  = (const float*)d_in[0];
    const float* We = (const float*)d_in[1];
    const float* be = (const float*)d_in[2];
    const float* Wg = (const float*)d_in[3];
    const float* bg = (const float*)d_in[4];
    float* out = (float*)d_out;

    cudaFuncSetAttribute(moe_wmma_kernel, cudaFuncAttributeMaxDynamicSharedMemorySize, SMEM_BYTES);

    prep_We_kernel<<<IN_DIM * NCOL / 4 / 256, 256>>>((const float4*)We);
    gate_kernel<<<BATCH / 16, 512>>>((const float4*)x, Wg, bg);
    moe_wmma_kernel<<<(BATCH / BM) * (NCOL / BN), NTHREADS, SMEM_BYTES>>>(be, out);
}

// round 7
// speedup vs baseline: 2.4879x; 2.0834x over previous
#include <cuda_runtime.h>
#include <cstdint>
#include <cstddef>

// ============================================================================
// Problem constants
// ============================================================================
static constexpr int BATCH  = 16384;
static constexpr int IN_DIM = 512;
static constexpr int UNITS  = 256;
static constexpr int NEXP   = 8;
static constexpr int NTASK  = 4;
static constexpr int NCOL   = UNITS * NEXP;   // 2048, n = u*8+e
static constexpr int GCOL   = NEXP * NTASK;   // 32,   g = e*4+t

// Fragment-block geometry (mma.m16n8k8)
static constexpr int MBLKS  = BATCH / 16;     // 1024
static constexpr int KBLKS  = IN_DIM / 8;     // 64
static constexpr int KBLK2S = IN_DIM / 16;    // 32
static constexpr int NBLKS  = NCOL / 8;       // 256

// Tiling
static constexpr int BM     = 128;            // 8 m_blks
static constexpr int BN     = 128;            // 16 n_blks
static constexpr int KC     = 32;             // 4 k_blks / 2 k_blk2s
static constexpr int KSTEPS = IN_DIM / KC;    // 16
static constexpr int STAGES = 3;
static constexpr int NTHREADS = 256;          // 8 warps, 2x4 warp grid (64x32 warp tiles)

// Shared memory (float4 units): stage = A(8*4*32) + B(16*2*32) = 2048 float4 = 32KB
static constexpr int A_STAGE_F4 = 8 * 4 * 32;     // 1024
static constexpr int B_STAGE_F4 = 16 * 2 * 32;    // 1024
static constexpr int STAGE_F4   = A_STAGE_F4 + B_STAGE_F4;  // 2048
static constexpr int HDR_F4     = 32;             // be slice (128 floats)
static constexpr int SMEM_F4    = HDR_F4 + STAGES * STAGE_F4;
static constexpr int SMEM_BYTES = SMEM_F4 * 16;   // 98816 (x2 CTA = 193 KB)
static constexpr int C_LD       = BN + 4;         // 132 (staging 128*132*4 = 67.6 KB)

// ============================================================================
// Device scratch (no allocations allowed)
// ============================================================================
__device__ float  g_gates[BATCH * GCOL];                  // softmaxed gates [b][e*4+t]
__device__ float4 g_xA  [(size_t)MBLKS * KBLKS * 32];     // A fragments (32 MB)
__device__ float4 g_WeB [(size_t)NBLKS * KBLK2S * 32];    // B fragments ( 4 MB)

// ============================================================================
// Helpers
// ============================================================================
__device__ __forceinline__ uint32_t smem_u32(const void* p) {
    uint32_t a;
    asm("{ .reg .u64 t; cvta.to.shared.u64 t, %1; cvt.u32.u64 %0, t; }" : "=r"(a) : "l"(p));
    return a;
}
__device__ __forceinline__ float tf32_rn(float f) {
    uint32_t o; asm("cvt.rn.tf32.f32 %0, %1;" : "=r"(o) : "f"(f));
    return __uint_as_float(o);
}
__device__ __forceinline__ void cp_async16(uint32_t dst, const void* src) {
    asm volatile("cp.async.cg.shared.global [%0], [%1], 16;\n" :: "r"(dst), "l"(src));
}
#define CP_COMMIT()       asm volatile("cp.async.commit_group;\n" ::: "memory")
#define CP_WAIT_GROUP_1() asm volatile("cp.async.wait_group 1;\n" ::: "memory")

// D += A(16x8) * B(8x8), tf32 operands, f32 accum
__device__ __forceinline__ void mma_tf32(float* c, const float4& a, float b0, float b1) {
    asm volatile(
        "mma.sync.aligned.m16n8k8.row.col.f32.tf32.tf32.f32 "
        "{%0,%1,%2,%3}, {%4,%5,%6,%7}, {%8,%9}, {%0,%1,%2,%3};"
        : "+f"(c[0]), "+f"(c[1]), "+f"(c[2]), "+f"(c[3])
        : "r"(__float_as_uint(a.x)), "r"(__float_as_uint(a.y)),
          "r"(__float_as_uint(a.z)), "r"(__float_as_uint(a.w)),
          "r"(__float_as_uint(b0)),  "r"(__float_as_uint(b1)));
}

// ============================================================================
// prep We: tf32-round + pack into B-fragment order.
// g_WeB[(n_blk*32 + k_blk2)*32 + lane] = {b0(k_even), b1(k_even), b0(k_odd), b1(k_odd)}
//   b0 = We[kb + tig][n], b1 = We[kb + tig + 4][n];  n = n_blk*8 + gr
// ============================================================================
__global__ void __launch_bounds__(256)
prep_We_kernel(const float* __restrict__ We) {
    const int n_blk = blockIdx.x;
    const int t = threadIdx.x;
    #pragma unroll
    for (int i = 0; i < 4; i++) {
        int slot = t + i * 256;            // 1024 slots = 32 k2 x 32 lanes
        int k2   = slot >> 5;
        int lane = slot & 31;
        int gr = lane >> 2, tig = lane & 3;
        int n  = n_blk * 8 + gr;
        int kb = k2 * 16;
        float4 v;
        v.x = tf32_rn(__ldg(We + (size_t)(kb + tig)      * NCOL + n));
        v.y = tf32_rn(__ldg(We + (size_t)(kb + tig + 4)  * NCOL + n));
        v.z = tf32_rn(__ldg(We + (size_t)(kb + 8 + tig)  * NCOL + n));
        v.w = tf32_rn(__ldg(We + (size_t)(kb + 12 + tig) * NCOL + n));
        g_WeB[((size_t)n_blk * KBLK2S + k2) * 32 + lane] = v;
    }
}

// ============================================================================
// Gating kernel: computes softmaxed gates AND writes x in A-fragment order.
// One block = 16 batch rows = one m_blk.
// g_xA[(m_blk*64 + k_blk)*32 + lane] = {a0,a1,a2,a3}
//   a0=(gr,tig) a1=(gr+8,tig) a2=(gr,tig+4) a3=(gr+8,tig+4), cols rel. k_blk*8
// ============================================================================
__global__ void __launch_bounds__(512)
gate_kernel(const float4* __restrict__ x4, const float* __restrict__ Wg,
            const float* __restrict__ bg) {
    __shared__ float xs[16][IN_DIM];
    __shared__ float ls[16][GCOL];
    const int tid = threadIdx.x;
    const int blk = blockIdx.x;            // m_blk
    const int b0  = blk * 16;

    // load + tf32-round into smem
    #pragma unroll
    for (int i = 0; i < 4; i++) {
        int idx = tid + i * 512;           // float4 index within 16x512 tile
        int rr = idx >> 7, c = idx & 127;
        float4 v = x4[(size_t)(b0 + rr) * (IN_DIM / 4) + c];
        v.x = tf32_rn(v.x); v.y = tf32_rn(v.y); v.z = tf32_rn(v.z); v.w = tf32_rn(v.w);
        *(float4*)&xs[rr][c * 4] = v;
    }
    __syncthreads();

    // write A fragments (2048 slots = 64 k_blk x 32 lanes)
    #pragma unroll
    for (int i = 0; i < 4; i++) {
        int slot = tid + i * 512;
        int k_blk = slot >> 5;
        int lane  = slot & 31;
        int gr = lane >> 2, tig = lane & 3;
        int kc = k_blk * 8;
        float4 v;
        v.x = xs[gr][kc + tig];
        v.y = xs[gr + 8][kc + tig];
        v.z = xs[gr][kc + tig + 4];
        v.w = xs[gr + 8][kc + tig + 4];
        g_xA[((size_t)blk * KBLKS + k_blk) * 32 + lane] = v;
    }

    // gate logits
    const int r = tid >> 5, g = tid & 31;
    float a0 = 0.f, a1 = 0.f, a2 = 0.f, a3 = 0.f;
    #pragma unroll 4
    for (int k = 0; k < IN_DIM; k += 4) {
        a0 += xs[r][k]     * Wg[(size_t)(k)     * GCOL + g];
        a1 += xs[r][k + 1] * Wg[(size_t)(k + 1) * GCOL + g];
        a2 += xs[r][k + 2] * Wg[(size_t)(k + 2) * GCOL + g];
        a3 += xs[r][k + 3] * Wg[(size_t)(k + 3) * GCOL + g];
    }
    ls[r][g] = (a0 + a1) + (a2 + a3) + bg[g];
    __syncthreads();

    if (tid < 64) {
        const int rr = tid >> 2, t = tid & 3;
        float v[NEXP], m = -3.4e38f;
        #pragma unroll
        for (int e = 0; e < NEXP; e++) { v[e] = ls[rr][e * 4 + t]; m = fmaxf(m, v[e]); }
        float den = 0.f;
        #pragma unroll
        for (int e = 0; e < NEXP; e++) { v[e] = expf(v[e] - m); den += v[e]; }
        const float inv = 1.f / den;
        #pragma unroll
        for (int e = 0; e < NEXP; e++)
            g_gates[(size_t)(b0 + rr) * GCOL + e * 4 + t] = v[e] * inv;
    }
}

// ============================================================================
// Main kernel: explicit mma.m16n8k8 tf32 with fragment-major smem (lds.128)
// 256 threads, warp grid 2(m) x 4(n), warp tile 64x32.
// ============================================================================
__global__ void __launch_bounds__(NTHREADS, 2)
moe_mma_kernel(const float* __restrict__ be, float* __restrict__ out) {
    extern __shared__ float4 smem4[];
    float*  sbe    = (float*)smem4;
    float4* stage0 = smem4 + HDR_F4;

    const int tid  = threadIdx.x;
    const int wid  = tid >> 5;
    const int lane = tid & 31;
    const int gr   = lane >> 2, tig = lane & 3;
    const int warp_m = wid >> 2;        // 0..1
    const int warp_n = wid & 3;         // 0..3

    const int n_tile = blockIdx.x & 15;
    const int b_tile = blockIdx.x >> 4;
    const int b0 = b_tile * BM;
    const int mb0 = b_tile * 8;         // global m_blk base
    const int nb0 = n_tile * 16;        // global n_blk base

    if (tid < BN) sbe[tid] = be[n_tile * BN + tid];

    float acc[4][4][4];                 // [mi][ni][frag]
    #pragma unroll
    for (int mi = 0; mi < 4; mi++)
        #pragma unroll
        for (int ni = 0; ni < 4; ni++)
            #pragma unroll
            for (int q = 0; q < 4; q++) acc[mi][ni][q] = 0.f;

    auto load_stage = [&](int slot, int kt) {
        float4* As = stage0 + slot * STAGE_F4;
        float4* Bs = As + A_STAGE_F4;
        const uint32_t aB = smem_u32(As);
        const uint32_t bB = smem_u32(Bs);
        // A: 1024 chunks; c = (mb_l*4 + kb_l)*32 + lane
        #pragma unroll
        for (int i = 0; i < 4; i++) {
            int c = tid + i * 256;
            int mb = c >> 7, rem = c & 127;
            size_t g = ((size_t)(mb0 + mb) * KBLKS + (kt * 4 + (rem >> 5))) * 32 + (rem & 31);
            cp_async16(aB + (uint32_t)c * 16, g_xA + g);
        }
        // B: 1024 chunks; c = (nb_l*2 + k2_l)*32 + lane
        #pragma unroll
        for (int i = 0; i < 4; i++) {
            int c = tid + i * 256;
            int nb = c >> 6, rem = c & 63;
            size_t g = ((size_t)(nb0 + nb) * KBLK2S + (kt * 2 + (rem >> 5))) * 32 + (rem & 31);
            cp_async16(bB + (uint32_t)c * 16, g_WeB + g);
        }
    };

    auto compute_stage = [&](int slot) {
        const float4* As = stage0 + slot * STAGE_F4;
        const float4* Bs = As + A_STAGE_F4;
        #pragma unroll
        for (int k2 = 0; k2 < 2; k2++) {
            float4 Bv[4];
            #pragma unroll
            for (int ni = 0; ni < 4; ni++)
                Bv[ni] = Bs[((warp_n * 4 + ni) * 2 + k2) * 32 + lane];
            #pragma unroll
            for (int half = 0; half < 2; half++) {
                const int ks = k2 * 2 + half;
                float4 Av[4];
                #pragma unroll
                for (int mi = 0; mi < 4; mi++)
                    Av[mi] = As[((warp_m * 4 + mi) * 4 + ks) * 32 + lane];
                #pragma unroll
                for (int mi = 0; mi < 4; mi++)
                    #pragma unroll
                    for (int ni = 0; ni < 4; ni++) {
                        if (half == 0) mma_tf32(acc[mi][ni], Av[mi], Bv[ni].x, Bv[ni].y);
                        else           mma_tf32(acc[mi][ni], Av[mi], Bv[ni].z, Bv[ni].w);
                    }
            }
        }
    };

    // Prologue
    load_stage(0, 0); CP_COMMIT();
    load_stage(1, 1); CP_COMMIT();

    // Main loop
    for (int kt = 0; kt < KSTEPS; kt++) {
        CP_WAIT_GROUP_1();
        __syncthreads();
        const int next = kt + 2;
        if (next < KSTEPS) load_stage(next % STAGES, next);
        CP_COMMIT();
        compute_stage(kt % STAGES);
    }

    // ------------------------------------------------------------------
    // Epilogue: stage C through smem, then bias+ReLU+gate combine
    // ------------------------------------------------------------------
    __syncthreads();
    float* Cs = (float*)stage0;   // 128 x 132 floats = 67.6 KB
    #pragma unroll
    for (int mi = 0; mi < 4; mi++) {
        #pragma unroll
        for (int ni = 0; ni < 4; ni++) {
            int row = warp_m * 64 + mi * 16 + gr;
            int col = warp_n * 32 + ni * 8 + 2 * tig;
            *(float2*)&Cs[row * C_LD + col]       = make_float2(acc[mi][ni][0], acc[mi][ni][1]);
            *(float2*)&Cs[(row + 8) * C_LD + col] = make_float2(acc[mi][ni][2], acc[mi][ni][3]);
        }
    }
    __syncthreads();

    const int r = tid >> 1;       // row in tile (0..127)
    const int h = tid & 1;        // column half (8 units each)
    const int b = b0 + r;

    float gate[GCOL];
    {
        const float4* gp = (const float4*)(g_gates + (size_t)b * GCOL);
        #pragma unroll
        for (int q = 0; q < 8; q++) ((float4*)gate)[q] = gp[q];
    }

    float accu[8][NTASK];
    #pragma unroll
    for (int u = 0; u < 8; u++)
        #pragma unroll
        for (int t = 0; t < NTASK; t++) accu[u][t] = 0.f;

    #pragma unroll
    for (int u = 0; u < 8; u++) {
        const int nl = (h * 8 + u) * 8;
        #pragma unroll
        for (int e = 0; e < NEXP; e++) {
            float v = Cs[r * C_LD + nl + e] + sbe[nl + e];
            v = fmaxf(v, 0.f);
            #pragma unroll
            for (int t = 0; t < NTASK; t++) accu[u][t] += v * gate[e * 4 + t];
        }
    }

    float* ob = out + (size_t)b * UNITS + n_tile * 16 + h * 8;
    #pragma unroll
    for (int t = 0; t < NTASK; t++) {
        float4 o0 = make_float4(accu[0][t], accu[1][t], accu[2][t], accu[3][t]);
        float4 o1 = make_float4(accu[4][t], accu[5][t], accu[6][t], accu[7][t]);
        *(float4*)(ob + (size_t)t * BATCH * UNITS)     = o0;
        *(float4*)(ob + (size_t)t * BATCH * UNITS + 4) = o1;
    }
}

// ============================================================================
// Launch
// ============================================================================
extern "C" void kernel_launch(void* const* d_in, const int* in_sizes, int n_in,
                              void* d_out, int out_size) {
    const float* x  = (const float*)d_in[0];
    const float* We = (const float*)d_in[1];
    const float* be = (const float*)d_in[2];
    const float* Wg = (const float*)d_in[3];
    const float* bg = (const float*)d_in[4];
    float* out = (float*)d_out;

    cudaFuncSetAttribute(moe_mma_kernel, cudaFuncAttributeMaxDynamicSharedMemorySize, SMEM_BYTES);

    prep_We_kernel<<<NBLKS, 256>>>(We);
    gate_kernel<<<MBLKS, 512>>>((const float4*)x, Wg, bg);
    moe_mma_kernel<<<(BATCH / BM) * (NCOL / BN), NTHREADS, SMEM_BYTES>>>(be, out);
}